// round 3
// baseline (speedup 1.0000x reference)
#include <cuda_runtime.h>
#include <cuda_bf16.h>
#include <cstdint>

#define B_ 4
#define S_ 1024
#define E_ 1024
#define H_ 16
#define D_ 64
#define BH_ 64
#define NPOS_ 129
#define QD_LD 132
#define SCALING_ 0.125f

typedef unsigned int u32;
typedef unsigned long long u64;

// Scratch (device globals; no runtime allocation allowed)
__device__ float g_q[B_*H_*S_*D_];      // [B,H,S,D]
__device__ float g_k[B_*H_*S_*D_];
__device__ float g_v[B_*H_*S_*D_];
__device__ float g_qd[BH_*S_*QD_LD];    // [BH,S,129(+pad)]
__device__ float g_attn[B_*S_*E_];      // [B,S,H*D]

// ---------------------------------------------------------------------------
// bf16 split helpers: x ~= hi + lo, both bf16.
// ---------------------------------------------------------------------------
__device__ __forceinline__ void bsplit(float x, u32& hb, u32& lb) {
    __nv_bfloat16 h = __float2bfloat16(x);
    float hf = __bfloat162float(h);
    __nv_bfloat16 l = __float2bfloat16(x - hf);
    hb = (u32)__bfloat16_as_ushort(h);
    lb = (u32)__bfloat16_as_ushort(l);
}

__device__ __forceinline__ void mma_bf16(float* c, u32 a0, u32 a1, u32 a2, u32 a3,
                                         u32 b0, u32 b1) {
    asm volatile(
        "mma.sync.aligned.m16n8k16.row.col.f32.bf16.bf16.f32 "
        "{%0,%1,%2,%3},{%4,%5,%6,%7},{%8,%9},{%0,%1,%2,%3};"
        : "+f"(c[0]), "+f"(c[1]), "+f"(c[2]), "+f"(c[3])
        : "r"(a0), "r"(a1), "r"(a2), "r"(a3), "r"(b0), "r"(b1));
}

// ---------------------------------------------------------------------------
// Smem layout: per BK=16 real-k tile.
//   A arrays (HH: packed (hi,hi); L0: packed (lo,0)): u64[row][12], 8 used.
//     u64 index p = g*4 + qc holds (slot j=g*8+qc, slot j=g*8+qc+4) as 2 u32.
//     Each u32 is the bf16x2 k'-pair for one real-k slot.
//   B arrays (HL: (hi,lo); H0: (hi,0)): same shape, rows = n.
// Fragment loads: a0a2 / a1a3 / b0b1 each one LDS.64, conflict-free (stride 24
// words -> phase bases {0,24,16,8} + even offsets < 8 are disjoint).
// ---------------------------------------------------------------------------

// stage A: thread owns row ar, 8 k-values starting at ac (0 or 8)
__device__ __forceinline__ void stageA_regs(float4 a0v, float4 a1v, int ar, int ac,
                                            u64* AsHH, u64* AsL0) {
    float fe[4] = {a0v.x, a0v.y, a0v.z, a0v.w};
    float fo[4] = {a1v.x, a1v.y, a1v.z, a1v.w};
    int base = ar * 12 + (ac >> 1);
#pragma unroll
    for (int i = 0; i < 4; i++) {
        u32 he, le, ho, lo2;
        bsplit(fe[i], he, le);
        bsplit(fo[i], ho, lo2);
        AsHH[base + i] = (u64)(he * 0x10001u) | ((u64)(ho * 0x10001u) << 32);
        AsL0[base + i] = (u64)le | ((u64)lo2 << 32);
    }
}

// stage B from NT layout: thread owns row br, 4 k-values at kq*4
__device__ __forceinline__ void stageB_nt(float4 v, int br, int kq,
                                          u64* BsHL, u64* BsH0) {
    u32* HL = (u32*)BsHL;
    u32* H0 = (u32*)BsH0;
    float fv[4] = {v.x, v.y, v.z, v.w};
#pragma unroll
    for (int i = 0; i < 4; i++) {
        int k = kq * 4 + i;
        int q = (k & 8) + ((k & 3) << 1) + ((k >> 2) & 1);
        u32 hb, lb;
        bsplit(fv[i], hb, lb);
        HL[br * 24 + q] = hb | (lb << 16);
        H0[br * 24 + q] = hb;
    }
}

// stage B from NN layout (pv: V[k][64]): thread owns k-row kr, 4 n at nc
__device__ __forceinline__ void stageB_nn(float4 v, int kr, int nc,
                                          u64* BsHL, u64* BsH0) {
    u32* HL = (u32*)BsHL;
    u32* H0 = (u32*)BsH0;
    int q = (kr & 8) + ((kr & 3) << 1) + ((kr >> 2) & 1);
    float fv[4] = {v.x, v.y, v.z, v.w};
#pragma unroll
    for (int i = 0; i < 4; i++) {
        u32 hb, lb;
        bsplit(fv[i], hb, lb);
        HL[(nc + i) * 24 + q] = hb | (lb << 16);
        H0[(nc + i) * 24 + q] = hb;
    }
}

// warp-tile compute over one BK=16 staged tile. warp tile 32x32: 2 mt x 4 nt.
__device__ __forceinline__ void compute16(const u64* AsHH, const u64* AsL0,
                                          const u64* BsHL, const u64* BsH0,
                                          int wm, int wn, int qr, int qc,
                                          float acc[2][4][4]) {
#pragma unroll
    for (int g = 0; g < 2; g++) {
        u64 ah[2][2], al[2][2];
#pragma unroll
        for (int mt = 0; mt < 2; mt++) {
            int m = wm * 32 + mt * 16 + qr;
            int idx = m * 12 + g * 4 + qc;
            int idx8 = idx + 8 * 12;
            ah[mt][0] = AsHH[idx];  ah[mt][1] = AsHH[idx8];
            al[mt][0] = AsL0[idx];  al[mt][1] = AsL0[idx8];
        }
#pragma unroll
        for (int nt = 0; nt < 4; nt++) {
            int n = wn * 32 + nt * 8 + qr;
            u64 bhl = BsHL[n * 12 + g * 4 + qc];
            u64 bh0 = BsH0[n * 12 + g * 4 + qc];
            u32 b0 = (u32)bhl, b1 = (u32)(bhl >> 32);
            u32 c0 = (u32)bh0, c1 = (u32)(bh0 >> 32);
#pragma unroll
            for (int mt = 0; mt < 2; mt++) {
                mma_bf16(acc[mt][nt],
                         (u32)ah[mt][0], (u32)ah[mt][1],
                         (u32)(ah[mt][0] >> 32), (u32)(ah[mt][1] >> 32), b0, b1);
                mma_bf16(acc[mt][nt],
                         (u32)al[mt][0], (u32)al[mt][1],
                         (u32)(al[mt][0] >> 32), (u32)(al[mt][1] >> 32), c0, c1);
            }
        }
    }
}

#define GEMM_PREAMBLE()                                        \
    __shared__ u64 AsHH[128*12], AsL0[128*12];                 \
    __shared__ u64 BsHL[64*12], BsH0[64*12];                   \
    int tid = threadIdx.x;                                     \
    int lane = tid & 31, wid = tid >> 5;                       \
    int wm = wid >> 1, wn = wid & 1;                           \
    int qr = lane >> 2, qc = lane & 3;                         \
    int ar = tid >> 1, ac = (tid & 1) * 8;                     \
    int br = tid >> 2, bq = tid & 3;                           \
    float acc[2][4][4];                                        \
    _Pragma("unroll") for (int i = 0; i < 2; i++)              \
    _Pragma("unroll") for (int j = 0; j < 4; j++)              \
    _Pragma("unroll") for (int e = 0; e < 4; e++) acc[i][j][e] = 0.f;

// ---------------------------------------------------------------------------
// Kernel 1: QKV projection (NT, M=4096 N=3072 K=1024), scatter epilogue.
// ---------------------------------------------------------------------------
__global__ __launch_bounds__(256) void qkv_gemm_kernel(
    const float* __restrict__ A, const float* __restrict__ W,
    const float* __restrict__ bias) {
    GEMM_PREAMBLE();
    int bm = blockIdx.y * 128, bn = blockIdx.x * 64;
    const float* Arow = A + (size_t)(bm + ar) * 1024 + ac;
    const float* Brow = W + (size_t)(bn + br) * 1024 + bq * 4;
    float4 pa0 = *(const float4*)(Arow);
    float4 pa1 = *(const float4*)(Arow + 4);
    float4 pb  = *(const float4*)(Brow);

    for (int k0 = 0; k0 < 1024; k0 += 16) {
        __syncthreads();
        stageA_regs(pa0, pa1, ar, ac, AsHH, AsL0);
        stageB_nt(pb, br, bq, BsHL, BsH0);
        __syncthreads();
        if (k0 + 16 < 1024) {
            pa0 = *(const float4*)(Arow + k0 + 16);
            pa1 = *(const float4*)(Arow + k0 + 20);
            pb  = *(const float4*)(Brow + k0 + 16);
        }
        compute16(AsHH, AsL0, BsHL, BsH0, wm, wn, qr, qc, acc);
    }

#pragma unroll
    for (int mt = 0; mt < 2; mt++)
#pragma unroll
        for (int nt = 0; nt < 4; nt++)
#pragma unroll
            for (int e = 0; e < 4; e++) {
                int m = bm + wm*32 + mt*16 + qr + (e >= 2 ? 8 : 0);
                int n = bn + wn*32 + nt*8 + 2*qc + (e & 1);
                float c = acc[mt][nt][e] + bias[n];
                int b = m >> 10, s = m & 1023;
                int part = n >> 10;
                int h = (n & 1023) >> 6;
                int d = n & 63;
                float* dst = (part == 0) ? g_q : ((part == 1) ? g_k : g_v);
                dst[(((size_t)(b*H_ + h))*S_ + s)*D_ + d] = c;
            }
}

// ---------------------------------------------------------------------------
// Kernel 2: qd[bh,l,p] = sum_d q[bh,l,d]*dist_emb[p,d]  (small, SIMT)
// ---------------------------------------------------------------------------
__global__ void qd_kernel(const float* __restrict__ de) {
    __shared__ float sde[NPOS_][D_];
    __shared__ float sq[32][D_];
    int tid = threadIdx.x;
    int bh = blockIdx.y;
    int l0 = blockIdx.x * 32;
    for (int i = tid; i < NPOS_*D_; i += 256) ((float*)sde)[i] = de[i];
    const float* qsrc = g_q + ((size_t)bh*S_ + l0)*D_;
    for (int i = tid; i < 32*D_; i += 256) ((float*)sq)[i] = qsrc[i];
    __syncthreads();
    for (int o = tid; o < 32*NPOS_; o += 256) {
        int rr = o / NPOS_, p = o - rr*NPOS_;
        float s = 0.f;
#pragma unroll
        for (int d = 0; d < D_; d++) s += sq[rr][d] * sde[p][d];
        g_qd[((size_t)bh*S_ + l0 + rr)*QD_LD + p] = s;
    }
}

// ---------------------------------------------------------------------------
// Kernel 3: scores (per-bh NT, M=N=1024, K=64) + qd bias epilogue
// ---------------------------------------------------------------------------
__global__ __launch_bounds__(256) void scores_kernel(float* __restrict__ wts) {
    GEMM_PREAMBLE();
    int bh = blockIdx.z;
    const float* Q = g_q + (size_t)bh*S_*D_;
    const float* K = g_k + (size_t)bh*S_*D_;
    int bm = blockIdx.y * 128, bn = blockIdx.x * 64;
    const float* Arow = Q + (size_t)(bm + ar) * 64 + ac;
    const float* Brow = K + (size_t)(bn + br) * 64 + bq * 4;
    float4 pa0 = *(const float4*)(Arow);
    float4 pa1 = *(const float4*)(Arow + 4);
    float4 pb  = *(const float4*)(Brow);

    for (int k0 = 0; k0 < 64; k0 += 16) {
        __syncthreads();
        stageA_regs(pa0, pa1, ar, ac, AsHH, AsL0);
        stageB_nt(pb, br, bq, BsHL, BsH0);
        __syncthreads();
        if (k0 + 16 < 64) {
            pa0 = *(const float4*)(Arow + k0 + 16);
            pa1 = *(const float4*)(Arow + k0 + 20);
            pb  = *(const float4*)(Brow + k0 + 16);
        }
        compute16(AsHH, AsL0, BsHL, BsH0, wm, wn, qr, qc, acc);
    }

    float* Wrow = wts + (size_t)bh*S_*S_;
#pragma unroll
    for (int mt = 0; mt < 2; mt++)
#pragma unroll
        for (int nt = 0; nt < 4; nt++)
#pragma unroll
            for (int e = 0; e < 4; e++) {
                int l = bm + wm*32 + mt*16 + qr + (e >= 2 ? 8 : 0);
                int r = bn + wn*32 + nt*8 + 2*qc + (e & 1);
                int dl = r - l;
                dl = dl < -64 ? -64 : (dl > 64 ? 64 : dl);
                float qdv = g_qd[((size_t)bh*S_ + l)*QD_LD + dl + 64];
                Wrow[(size_t)l*S_ + r] = (acc[mt][nt][e] + qdv) * SCALING_;
            }
}

// ---------------------------------------------------------------------------
// Kernel 4: row softmax (near HBM roofline already)
// ---------------------------------------------------------------------------
__global__ void softmax_kernel(float* __restrict__ wts) {
    float* row = wts + (size_t)blockIdx.x * 1024;
    int tid = threadIdx.x;
    float4 v = ((float4*)row)[tid];
    float m = fmaxf(fmaxf(v.x, v.y), fmaxf(v.z, v.w));
#pragma unroll
    for (int o = 16; o > 0; o >>= 1) m = fmaxf(m, __shfl_xor_sync(0xffffffffu, m, o));
    __shared__ float sred[8];
    __shared__ float sred2[8];
    int wid = tid >> 5, lane = tid & 31;
    if (lane == 0) sred[wid] = m;
    __syncthreads();
    float mm = sred[0];
#pragma unroll
    for (int i = 1; i < 8; i++) mm = fmaxf(mm, sred[i]);
    v.x = __expf(v.x - mm); v.y = __expf(v.y - mm);
    v.z = __expf(v.z - mm); v.w = __expf(v.w - mm);
    float s = v.x + v.y + v.z + v.w;
#pragma unroll
    for (int o = 16; o > 0; o >>= 1) s += __shfl_xor_sync(0xffffffffu, s, o);
    if (lane == 0) sred2[wid] = s;
    __syncthreads();
    float tot = 0.f;
#pragma unroll
    for (int i = 0; i < 8; i++) tot += sred2[i];
    float inv = 1.0f / tot;
    v.x *= inv; v.y *= inv; v.z *= inv; v.w *= inv;
    ((float4*)row)[tid] = v;
}

// ---------------------------------------------------------------------------
// Kernel 5: PV (per-bh NN, M=1024 N=64 K=1024) -> g_attn [B,S,H*D]
// ---------------------------------------------------------------------------
__global__ __launch_bounds__(256) void pv_kernel(const float* __restrict__ wts) {
    GEMM_PREAMBLE();
    (void)br; (void)bq;
    int bh = blockIdx.y;
    int bm = blockIdx.x * 128;
    const float* Wm = wts + (size_t)bh*S_*S_;
    const float* V = g_v + (size_t)bh*S_*D_;
    int kr = tid & 15, nc = (tid >> 4) * 4;
    const float* Arow = Wm + (size_t)(bm + ar) * 1024 + ac;
    const float* Brow = V + (size_t)kr * 64 + nc;
    float4 pa0 = *(const float4*)(Arow);
    float4 pa1 = *(const float4*)(Arow + 4);
    float4 pb  = *(const float4*)(Brow);

    for (int k0 = 0; k0 < 1024; k0 += 16) {
        __syncthreads();
        stageA_regs(pa0, pa1, ar, ac, AsHH, AsL0);
        stageB_nn(pb, kr, nc, BsHL, BsH0);
        __syncthreads();
        if (k0 + 16 < 1024) {
            pa0 = *(const float4*)(Arow + k0 + 16);
            pa1 = *(const float4*)(Arow + k0 + 20);
            pb  = *(const float4*)(Brow + (size_t)(k0 + 16) * 64);
        }
        compute16(AsHH, AsL0, BsHL, BsH0, wm, wn, qr, qc, acc);
    }

    int b = bh >> 4, h = bh & 15;
#pragma unroll
    for (int mt = 0; mt < 2; mt++)
#pragma unroll
        for (int nt = 0; nt < 4; nt++)
#pragma unroll
            for (int e = 0; e < 4; e++) {
                int l = bm + wm*32 + mt*16 + qr + (e >= 2 ? 8 : 0);
                int d = wn*32 + nt*8 + 2*qc + (e & 1);
                g_attn[(((size_t)b*S_ + l)*H_ + h)*D_ + d] = acc[mt][nt][e];
            }
}

// ---------------------------------------------------------------------------
// Kernel 6: output projection (NT, M=4096 N=1024 K=1024)
// ---------------------------------------------------------------------------
__global__ __launch_bounds__(256) void outproj_kernel(
    const float* __restrict__ Wm, const float* __restrict__ bias,
    float* __restrict__ out) {
    GEMM_PREAMBLE();
    int bm = blockIdx.y * 128, bn = blockIdx.x * 64;
    const float* Arow = g_attn + (size_t)(bm + ar) * 1024 + ac;
    const float* Brow = Wm + (size_t)(bn + br) * 1024 + bq * 4;
    float4 pa0 = *(const float4*)(Arow);
    float4 pa1 = *(const float4*)(Arow + 4);
    float4 pb  = *(const float4*)(Brow);

    for (int k0 = 0; k0 < 1024; k0 += 16) {
        __syncthreads();
        stageA_regs(pa0, pa1, ar, ac, AsHH, AsL0);
        stageB_nt(pb, br, bq, BsHL, BsH0);
        __syncthreads();
        if (k0 + 16 < 1024) {
            pa0 = *(const float4*)(Arow + k0 + 16);
            pa1 = *(const float4*)(Arow + k0 + 20);
            pb  = *(const float4*)(Brow + k0 + 16);
        }
        compute16(AsHH, AsL0, BsHL, BsH0, wm, wn, qr, qc, acc);
    }

#pragma unroll
    for (int mt = 0; mt < 2; mt++)
#pragma unroll
        for (int nt = 0; nt < 4; nt++)
#pragma unroll
            for (int e = 0; e < 4; e++) {
                int m = bm + wm*32 + mt*16 + qr + (e >= 2 ? 8 : 0);
                int n = bn + wn*32 + nt*8 + 2*qc + (e & 1);
                out[(size_t)m*1024 + n] = acc[mt][nt][e] + bias[n];
            }
}

// ---------------------------------------------------------------------------
extern "C" void kernel_launch(void* const* d_in, const int* in_sizes, int n_in,
                              void* d_out, int out_size) {
    const float* hs       = (const float*)d_in[0];  // [4,1024,1024]
    const float* qkv_w    = (const float*)d_in[1];  // [3072,1024]
    const float* qkv_b    = (const float*)d_in[2];  // [3072]
    const float* out_w    = (const float*)d_in[3];  // [1024,1024]
    const float* out_b    = (const float*)d_in[4];  // [1024]
    const float* dist_emb = (const float*)d_in[5];  // [129,64]

    float* out = (float*)d_out;                      // attn_output [4,1024,1024]
    float* wts = out + (size_t)B_*S_*E_;             // attn_weights [4,16,1024,1024]

    qkv_gemm_kernel<<<dim3(48, 32), 256>>>(hs, qkv_w, qkv_b);
    qd_kernel<<<dim3(32, BH_), 256>>>(dist_emb);
    scores_kernel<<<dim3(16, 8, BH_), 256>>>(wts);
    softmax_kernel<<<BH_*S_, 256>>>(wts);
    pv_kernel<<<dim3(8, BH_), 256>>>(wts);
    outproj_kernel<<<dim3(16, 32), 256>>>(out_w, out_b, out);
}

// round 4
// speedup vs baseline: 1.0012x; 1.0012x over previous
#include <cuda_runtime.h>
#include <cuda_bf16.h>
#include <cstdint>

#define B_ 4
#define S_ 1024
#define E_ 1024
#define H_ 16
#define D_ 64
#define BH_ 64
#define NPOS_ 129
#define QD_LD 132
#define SCALING_ 0.125f

typedef unsigned int u32;
typedef unsigned long long u64;

// Scratch (device globals; no runtime allocation allowed)
__device__ float g_q[B_*H_*S_*D_];      // [B,H,S,D]
__device__ float g_k[B_*H_*S_*D_];
__device__ float g_v[B_*H_*S_*D_];
__device__ float g_qd[BH_*S_*QD_LD];    // [BH,S,129(+pad)]
__device__ float g_attn[B_*S_*E_];      // [B,S,H*D]

// ---------------------------------------------------------------------------
// bf16 split helpers: x ~= hi + lo, both bf16.
// ---------------------------------------------------------------------------
__device__ __forceinline__ void bsplit(float x, u32& hb, u32& lb) {
    __nv_bfloat16 h = __float2bfloat16(x);
    float hf = __bfloat162float(h);
    __nv_bfloat16 l = __float2bfloat16(x - hf);
    hb = (u32)__bfloat16_as_ushort(h);
    lb = (u32)__bfloat16_as_ushort(l);
}

__device__ __forceinline__ void mma_bf16(float* c, u32 a0, u32 a1, u32 a2, u32 a3,
                                         u32 b0, u32 b1) {
    asm volatile(
        "mma.sync.aligned.m16n8k16.row.col.f32.bf16.bf16.f32 "
        "{%0,%1,%2,%3},{%4,%5,%6,%7},{%8,%9},{%0,%1,%2,%3};"
        : "+f"(c[0]), "+f"(c[1]), "+f"(c[2]), "+f"(c[3])
        : "r"(a0), "r"(a1), "r"(a2), "r"(a3), "r"(b0), "r"(b1));
}

// ---------------------------------------------------------------------------
// Smem layout: per BK=16 real-k tile.
//   A arrays (HH: packed (hi,hi); L0: packed (lo,0)): u64[row][12], 8 used.
//     u64 index p = g*4 + qc holds (slot j=g*8+qc, slot j=g*8+qc+4) as 2 u32.
//     Each u32 is the bf16x2 k'-pair for one real-k slot.
//   B arrays (HL: (hi,lo); H0: (hi,0)): same shape, rows = n.
// Fragment loads: a0a2 / a1a3 / b0b1 each one LDS.64, conflict-free (stride 24
// words -> phase bases {0,24,16,8} + even offsets < 8 are disjoint).
// ---------------------------------------------------------------------------

// stage A: thread owns row ar, 8 k-values starting at ac (0 or 8)
__device__ __forceinline__ void stageA_regs(float4 a0v, float4 a1v, int ar, int ac,
                                            u64* AsHH, u64* AsL0) {
    float fe[4] = {a0v.x, a0v.y, a0v.z, a0v.w};
    float fo[4] = {a1v.x, a1v.y, a1v.z, a1v.w};
    int base = ar * 12 + (ac >> 1);
#pragma unroll
    for (int i = 0; i < 4; i++) {
        u32 he, le, ho, lo2;
        bsplit(fe[i], he, le);
        bsplit(fo[i], ho, lo2);
        AsHH[base + i] = (u64)(he * 0x10001u) | ((u64)(ho * 0x10001u) << 32);
        AsL0[base + i] = (u64)le | ((u64)lo2 << 32);
    }
}

// stage B from NT layout: thread owns row br, 4 k-values at kq*4
__device__ __forceinline__ void stageB_nt(float4 v, int br, int kq,
                                          u64* BsHL, u64* BsH0) {
    u32* HL = (u32*)BsHL;
    u32* H0 = (u32*)BsH0;
    float fv[4] = {v.x, v.y, v.z, v.w};
#pragma unroll
    for (int i = 0; i < 4; i++) {
        int k = kq * 4 + i;
        int q = (k & 8) + ((k & 3) << 1) + ((k >> 2) & 1);
        u32 hb, lb;
        bsplit(fv[i], hb, lb);
        HL[br * 24 + q] = hb | (lb << 16);
        H0[br * 24 + q] = hb;
    }
}

// stage B from NN layout (pv: V[k][64]): thread owns k-row kr, 4 n at nc
__device__ __forceinline__ void stageB_nn(float4 v, int kr, int nc,
                                          u64* BsHL, u64* BsH0) {
    u32* HL = (u32*)BsHL;
    u32* H0 = (u32*)BsH0;
    int q = (kr & 8) + ((kr & 3) << 1) + ((kr >> 2) & 1);
    float fv[4] = {v.x, v.y, v.z, v.w};
#pragma unroll
    for (int i = 0; i < 4; i++) {
        u32 hb, lb;
        bsplit(fv[i], hb, lb);
        HL[(nc + i) * 24 + q] = hb | (lb << 16);
        H0[(nc + i) * 24 + q] = hb;
    }
}

// warp-tile compute over one BK=16 staged tile. warp tile 32x32: 2 mt x 4 nt.
__device__ __forceinline__ void compute16(const u64* AsHH, const u64* AsL0,
                                          const u64* BsHL, const u64* BsH0,
                                          int wm, int wn, int qr, int qc,
                                          float acc[2][4][4]) {
#pragma unroll
    for (int g = 0; g < 2; g++) {
        u64 ah[2][2], al[2][2];
#pragma unroll
        for (int mt = 0; mt < 2; mt++) {
            int m = wm * 32 + mt * 16 + qr;
            int idx = m * 12 + g * 4 + qc;
            int idx8 = idx + 8 * 12;
            ah[mt][0] = AsHH[idx];  ah[mt][1] = AsHH[idx8];
            al[mt][0] = AsL0[idx];  al[mt][1] = AsL0[idx8];
        }
#pragma unroll
        for (int nt = 0; nt < 4; nt++) {
            int n = wn * 32 + nt * 8 + qr;
            u64 bhl = BsHL[n * 12 + g * 4 + qc];
            u64 bh0 = BsH0[n * 12 + g * 4 + qc];
            u32 b0 = (u32)bhl, b1 = (u32)(bhl >> 32);
            u32 c0 = (u32)bh0, c1 = (u32)(bh0 >> 32);
#pragma unroll
            for (int mt = 0; mt < 2; mt++) {
                mma_bf16(acc[mt][nt],
                         (u32)ah[mt][0], (u32)ah[mt][1],
                         (u32)(ah[mt][0] >> 32), (u32)(ah[mt][1] >> 32), b0, b1);
                mma_bf16(acc[mt][nt],
                         (u32)al[mt][0], (u32)al[mt][1],
                         (u32)(al[mt][0] >> 32), (u32)(al[mt][1] >> 32), c0, c1);
            }
        }
    }
}

#define GEMM_PREAMBLE()                                        \
    __shared__ u64 AsHH[128*12], AsL0[128*12];                 \
    __shared__ u64 BsHL[64*12], BsH0[64*12];                   \
    int tid = threadIdx.x;                                     \
    int lane = tid & 31, wid = tid >> 5;                       \
    int wm = wid >> 1, wn = wid & 1;                           \
    int qr = lane >> 2, qc = lane & 3;                         \
    int ar = tid >> 1, ac = (tid & 1) * 8;                     \
    int br = tid >> 2, bq = tid & 3;                           \
    float acc[2][4][4];                                        \
    _Pragma("unroll") for (int i = 0; i < 2; i++)              \
    _Pragma("unroll") for (int j = 0; j < 4; j++)              \
    _Pragma("unroll") for (int e = 0; e < 4; e++) acc[i][j][e] = 0.f;

// ---------------------------------------------------------------------------
// Kernel 1: QKV projection (NT, M=4096 N=3072 K=1024), scatter epilogue.
// ---------------------------------------------------------------------------
__global__ __launch_bounds__(256) void qkv_gemm_kernel(
    const float* __restrict__ A, const float* __restrict__ W,
    const float* __restrict__ bias) {
    GEMM_PREAMBLE();
    int bm = blockIdx.y * 128, bn = blockIdx.x * 64;
    const float* Arow = A + (size_t)(bm + ar) * 1024 + ac;
    const float* Brow = W + (size_t)(bn + br) * 1024 + bq * 4;
    float4 pa0 = *(const float4*)(Arow);
    float4 pa1 = *(const float4*)(Arow + 4);
    float4 pb  = *(const float4*)(Brow);

    for (int k0 = 0; k0 < 1024; k0 += 16) {
        __syncthreads();
        stageA_regs(pa0, pa1, ar, ac, AsHH, AsL0);
        stageB_nt(pb, br, bq, BsHL, BsH0);
        __syncthreads();
        if (k0 + 16 < 1024) {
            pa0 = *(const float4*)(Arow + k0 + 16);
            pa1 = *(const float4*)(Arow + k0 + 20);
            pb  = *(const float4*)(Brow + k0 + 16);
        }
        compute16(AsHH, AsL0, BsHL, BsH0, wm, wn, qr, qc, acc);
    }

#pragma unroll
    for (int mt = 0; mt < 2; mt++)
#pragma unroll
        for (int nt = 0; nt < 4; nt++)
#pragma unroll
            for (int e = 0; e < 4; e++) {
                int m = bm + wm*32 + mt*16 + qr + (e >= 2 ? 8 : 0);
                int n = bn + wn*32 + nt*8 + 2*qc + (e & 1);
                float c = acc[mt][nt][e] + bias[n];
                int b = m >> 10, s = m & 1023;
                int part = n >> 10;
                int h = (n & 1023) >> 6;
                int d = n & 63;
                float* dst = (part == 0) ? g_q : ((part == 1) ? g_k : g_v);
                dst[(((size_t)(b*H_ + h))*S_ + s)*D_ + d] = c;
            }
}

// ---------------------------------------------------------------------------
// Kernel 2: qd[bh,l,p] = sum_d q[bh,l,d]*dist_emb[p,d]  (small, SIMT)
// ---------------------------------------------------------------------------
__global__ void qd_kernel(const float* __restrict__ de) {
    __shared__ float sde[NPOS_][D_];
    __shared__ float sq[32][D_];
    int tid = threadIdx.x;
    int bh = blockIdx.y;
    int l0 = blockIdx.x * 32;
    for (int i = tid; i < NPOS_*D_; i += 256) ((float*)sde)[i] = de[i];
    const float* qsrc = g_q + ((size_t)bh*S_ + l0)*D_;
    for (int i = tid; i < 32*D_; i += 256) ((float*)sq)[i] = qsrc[i];
    __syncthreads();
    for (int o = tid; o < 32*NPOS_; o += 256) {
        int rr = o / NPOS_, p = o - rr*NPOS_;
        float s = 0.f;
#pragma unroll
        for (int d = 0; d < D_; d++) s += sq[rr][d] * sde[p][d];
        g_qd[((size_t)bh*S_ + l0 + rr)*QD_LD + p] = s;
    }
}

// ---------------------------------------------------------------------------
// Kernel 3: scores (per-bh NT, M=N=1024, K=64) + qd bias epilogue
// ---------------------------------------------------------------------------
__global__ __launch_bounds__(256) void scores_kernel(float* __restrict__ wts) {
    GEMM_PREAMBLE();
    int bh = blockIdx.z;
    const float* Q = g_q + (size_t)bh*S_*D_;
    const float* K = g_k + (size_t)bh*S_*D_;
    int bm = blockIdx.y * 128, bn = blockIdx.x * 64;
    const float* Arow = Q + (size_t)(bm + ar) * 64 + ac;
    const float* Brow = K + (size_t)(bn + br) * 64 + bq * 4;
    float4 pa0 = *(const float4*)(Arow);
    float4 pa1 = *(const float4*)(Arow + 4);
    float4 pb  = *(const float4*)(Brow);

    for (int k0 = 0; k0 < 64; k0 += 16) {
        __syncthreads();
        stageA_regs(pa0, pa1, ar, ac, AsHH, AsL0);
        stageB_nt(pb, br, bq, BsHL, BsH0);
        __syncthreads();
        if (k0 + 16 < 64) {
            pa0 = *(const float4*)(Arow + k0 + 16);
            pa1 = *(const float4*)(Arow + k0 + 20);
            pb  = *(const float4*)(Brow + k0 + 16);
        }
        compute16(AsHH, AsL0, BsHL, BsH0, wm, wn, qr, qc, acc);
    }

    float* Wrow = wts + (size_t)bh*S_*S_;
#pragma unroll
    for (int mt = 0; mt < 2; mt++)
#pragma unroll
        for (int nt = 0; nt < 4; nt++)
#pragma unroll
            for (int e = 0; e < 4; e++) {
                int l = bm + wm*32 + mt*16 + qr + (e >= 2 ? 8 : 0);
                int r = bn + wn*32 + nt*8 + 2*qc + (e & 1);
                int dl = r - l;
                dl = dl < -64 ? -64 : (dl > 64 ? 64 : dl);
                float qdv = g_qd[((size_t)bh*S_ + l)*QD_LD + dl + 64];
                Wrow[(size_t)l*S_ + r] = (acc[mt][nt][e] + qdv) * SCALING_;
            }
}

// ---------------------------------------------------------------------------
// Kernel 4: row softmax (near HBM roofline already)
// ---------------------------------------------------------------------------
__global__ void softmax_kernel(float* __restrict__ wts) {
    float* row = wts + (size_t)blockIdx.x * 1024;
    int tid = threadIdx.x;
    float4 v = ((float4*)row)[tid];
    float m = fmaxf(fmaxf(v.x, v.y), fmaxf(v.z, v.w));
#pragma unroll
    for (int o = 16; o > 0; o >>= 1) m = fmaxf(m, __shfl_xor_sync(0xffffffffu, m, o));
    __shared__ float sred[8];
    __shared__ float sred2[8];
    int wid = tid >> 5, lane = tid & 31;
    if (lane == 0) sred[wid] = m;
    __syncthreads();
    float mm = sred[0];
#pragma unroll
    for (int i = 1; i < 8; i++) mm = fmaxf(mm, sred[i]);
    v.x = __expf(v.x - mm); v.y = __expf(v.y - mm);
    v.z = __expf(v.z - mm); v.w = __expf(v.w - mm);
    float s = v.x + v.y + v.z + v.w;
#pragma unroll
    for (int o = 16; o > 0; o >>= 1) s += __shfl_xor_sync(0xffffffffu, s, o);
    if (lane == 0) sred2[wid] = s;
    __syncthreads();
    float tot = 0.f;
#pragma unroll
    for (int i = 0; i < 8; i++) tot += sred2[i];
    float inv = 1.0f / tot;
    v.x *= inv; v.y *= inv; v.z *= inv; v.w *= inv;
    ((float4*)row)[tid] = v;
}

// ---------------------------------------------------------------------------
// Kernel 5: PV (per-bh NN, M=1024 N=64 K=1024) -> g_attn [B,S,H*D]
// ---------------------------------------------------------------------------
__global__ __launch_bounds__(256) void pv_kernel(const float* __restrict__ wts) {
    GEMM_PREAMBLE();
    (void)br; (void)bq;
    int bh = blockIdx.y;
    int bm = blockIdx.x * 128;
    const float* Wm = wts + (size_t)bh*S_*S_;
    const float* V = g_v + (size_t)bh*S_*D_;
    int kr = tid & 15, nc = (tid >> 4) * 4;
    const float* Arow = Wm + (size_t)(bm + ar) * 1024 + ac;
    const float* Brow = V + (size_t)kr * 64 + nc;
    float4 pa0 = *(const float4*)(Arow);
    float4 pa1 = *(const float4*)(Arow + 4);
    float4 pb  = *(const float4*)(Brow);

    for (int k0 = 0; k0 < 1024; k0 += 16) {
        __syncthreads();
        stageA_regs(pa0, pa1, ar, ac, AsHH, AsL0);
        stageB_nn(pb, kr, nc, BsHL, BsH0);
        __syncthreads();
        if (k0 + 16 < 1024) {
            pa0 = *(const float4*)(Arow + k0 + 16);
            pa1 = *(const float4*)(Arow + k0 + 20);
            pb  = *(const float4*)(Brow + (size_t)(k0 + 16) * 64);
        }
        compute16(AsHH, AsL0, BsHL, BsH0, wm, wn, qr, qc, acc);
    }

    int b = bh >> 4, h = bh & 15;
#pragma unroll
    for (int mt = 0; mt < 2; mt++)
#pragma unroll
        for (int nt = 0; nt < 4; nt++)
#pragma unroll
            for (int e = 0; e < 4; e++) {
                int l = bm + wm*32 + mt*16 + qr + (e >= 2 ? 8 : 0);
                int d = wn*32 + nt*8 + 2*qc + (e & 1);
                g_attn[(((size_t)b*S_ + l)*H_ + h)*D_ + d] = acc[mt][nt][e];
            }
}

// ---------------------------------------------------------------------------
// Kernel 6: output projection (NT, M=4096 N=1024 K=1024)
// ---------------------------------------------------------------------------
__global__ __launch_bounds__(256) void outproj_kernel(
    const float* __restrict__ Wm, const float* __restrict__ bias,
    float* __restrict__ out) {
    GEMM_PREAMBLE();
    int bm = blockIdx.y * 128, bn = blockIdx.x * 64;
    const float* Arow = g_attn + (size_t)(bm + ar) * 1024 + ac;
    const float* Brow = Wm + (size_t)(bn + br) * 1024 + bq * 4;
    float4 pa0 = *(const float4*)(Arow);
    float4 pa1 = *(const float4*)(Arow + 4);
    float4 pb  = *(const float4*)(Brow);

    for (int k0 = 0; k0 < 1024; k0 += 16) {
        __syncthreads();
        stageA_regs(pa0, pa1, ar, ac, AsHH, AsL0);
        stageB_nt(pb, br, bq, BsHL, BsH0);
        __syncthreads();
        if (k0 + 16 < 1024) {
            pa0 = *(const float4*)(Arow + k0 + 16);
            pa1 = *(const float4*)(Arow + k0 + 20);
            pb  = *(const float4*)(Brow + k0 + 16);
        }
        compute16(AsHH, AsL0, BsHL, BsH0, wm, wn, qr, qc, acc);
    }

#pragma unroll
    for (int mt = 0; mt < 2; mt++)
#pragma unroll
        for (int nt = 0; nt < 4; nt++)
#pragma unroll
            for (int e = 0; e < 4; e++) {
                int m = bm + wm*32 + mt*16 + qr + (e >= 2 ? 8 : 0);
                int n = bn + wn*32 + nt*8 + 2*qc + (e & 1);
                out[(size_t)m*1024 + n] = acc[mt][nt][e] + bias[n];
            }
}

// ---------------------------------------------------------------------------
extern "C" void kernel_launch(void* const* d_in, const int* in_sizes, int n_in,
                              void* d_out, int out_size) {
    const float* hs       = (const float*)d_in[0];  // [4,1024,1024]
    const float* qkv_w    = (const float*)d_in[1];  // [3072,1024]
    const float* qkv_b    = (const float*)d_in[2];  // [3072]
    const float* out_w    = (const float*)d_in[3];  // [1024,1024]
    const float* out_b    = (const float*)d_in[4];  // [1024]
    const float* dist_emb = (const float*)d_in[5];  // [129,64]

    float* out = (float*)d_out;                      // attn_output [4,1024,1024]
    float* wts = out + (size_t)B_*S_*E_;             // attn_weights [4,16,1024,1024]

    qkv_gemm_kernel<<<dim3(48, 32), 256>>>(hs, qkv_w, qkv_b);
    qd_kernel<<<dim3(32, BH_), 256>>>(dist_emb);
    scores_kernel<<<dim3(16, 8, BH_), 256>>>(wts);
    softmax_kernel<<<BH_*S_, 256>>>(wts);
    pv_kernel<<<dim3(8, BH_), 256>>>(wts);
    outproj_kernel<<<dim3(16, 32), 256>>>(out_w, out_b, out);
}